// round 3
// baseline (speedup 1.0000x reference)
#include <cuda_runtime.h>
#include <math_constants.h>

// Inputs: query_points [N,3] f32, ref_points [M,3] f32, ref_flow [M,3] f32 ; out [N,3] f32
// Shape: N=32768, M=16384 (general up to bounds below).

#define NMAX  32768
#define MMAX  16384
#define TILE  1024
#define KNN   8
#define SPLIT 8

__device__ float4 g_refs[MMAX];
__device__ float g_ps[SPLIT][KNN][NMAX];
__device__ int   g_pi[SPLIT][KNN][NMAX];

__global__ void prep_refs_kernel(const float* __restrict__ ref, int M) {
    int i = blockIdx.x * blockDim.x + threadIdx.x;
    if (i < M) {
        float x = ref[3 * i + 0];
        float y = ref[3 * i + 1];
        float z = ref[3 * i + 2];
        g_refs[i] = make_float4(x, y, z, fmaf(x, x, fmaf(y, y, z * z)));
    }
}

// Phase 1: each thread owns TWO queries (qa, qb); each block scans one M-slice.
// score = |r|^2 - 2 q.r  (monotone in squared distance; |q|^2 added in phase 2).
__global__ void __launch_bounds__(256, 4) knn_partial_kernel(
    const float* __restrict__ qpts, int N, int M, int H)
{
    __shared__ float4 s_ref[TILE];

    const int t  = blockIdx.x * blockDim.x + threadIdx.x;
    const int qa = t;            // [0, H)
    const int qb = t + H;        // [H, N)
    const int s  = blockIdx.y;
    const int Ms = (M + SPLIT - 1) / SPLIT;
    const int lo = s * Ms;
    const int hi = min(lo + Ms, M);

    float ax = 0.f, ay = 0.f, az = 0.f, bx = 0.f, by = 0.f, bz = 0.f;
    if (qa < H) {
        ax = qpts[3 * qa + 0]; ay = qpts[3 * qa + 1]; az = qpts[3 * qa + 2];
    }
    if (qb < N) {
        bx = qpts[3 * qb + 0]; by = qpts[3 * qb + 1]; bz = qpts[3 * qb + 2];
    }
    const float nax = -2.f * ax, nay = -2.f * ay, naz = -2.f * az;
    const float nbx = -2.f * bx, nby = -2.f * by, nbz = -2.f * bz;

    float ad[KNN], bd[KNN];
    int   ai[KNN], bi[KNN];
#pragma unroll
    for (int k = 0; k < KNN; ++k) {
        ad[k] = CUDART_INF_F; ai[k] = 0;
        bd[k] = CUDART_INF_F; bi[k] = 0;
    }

    for (int base = lo; base < hi; base += TILE) {
        int cnt = min(TILE, hi - base);
        __syncthreads();
        for (int j = threadIdx.x; j < TILE; j += blockDim.x) {
            s_ref[j] = (j < cnt) ? g_refs[base + j]
                                 : make_float4(0.f, 0.f, 0.f, CUDART_INF_F);
        }
        __syncthreads();

        for (int j = 0; j < TILE; j += 4) {
            float4 r0 = s_ref[j + 0];
            float4 r1 = s_ref[j + 1];
            float4 r2 = s_ref[j + 2];
            float4 r3 = s_ref[j + 3];
            // query A scores
            float a0 = fmaf(r0.x, nax, fmaf(r0.y, nay, fmaf(r0.z, naz, r0.w)));
            float a1 = fmaf(r1.x, nax, fmaf(r1.y, nay, fmaf(r1.z, naz, r1.w)));
            float a2 = fmaf(r2.x, nax, fmaf(r2.y, nay, fmaf(r2.z, naz, r2.w)));
            float a3 = fmaf(r3.x, nax, fmaf(r3.y, nay, fmaf(r3.z, naz, r3.w)));
            // query B scores (independent chain — fills A's latency)
            float b0 = fmaf(r0.x, nbx, fmaf(r0.y, nby, fmaf(r0.z, nbz, r0.w)));
            float b1 = fmaf(r1.x, nbx, fmaf(r1.y, nby, fmaf(r1.z, nbz, r1.w)));
            float b2 = fmaf(r2.x, nbx, fmaf(r2.y, nby, fmaf(r2.z, nbz, r2.w)));
            float b3 = fmaf(r3.x, nbx, fmaf(r3.y, nby, fmaf(r3.z, nbz, r3.w)));

            float ma = fminf(fminf(a0, a1), fminf(a2, a3));
            float mb = fminf(fminf(b0, b1), fminf(b2, b3));

            if (ma < ad[KNN - 1]) {
                float sv[4] = {a0, a1, a2, a3};
#pragma unroll
                for (int u = 0; u < 4; ++u) {
                    if (sv[u] < ad[KNN - 1]) {
                        ad[KNN - 1] = sv[u]; ai[KNN - 1] = base + j + u;
#pragma unroll
                        for (int k = KNN - 1; k > 0; --k) {
                            if (ad[k] < ad[k - 1]) {
                                float td = ad[k]; ad[k] = ad[k - 1]; ad[k - 1] = td;
                                int   ti = ai[k]; ai[k] = ai[k - 1]; ai[k - 1] = ti;
                            }
                        }
                    }
                }
            }
            if (mb < bd[KNN - 1]) {
                float sv[4] = {b0, b1, b2, b3};
#pragma unroll
                for (int u = 0; u < 4; ++u) {
                    if (sv[u] < bd[KNN - 1]) {
                        bd[KNN - 1] = sv[u]; bi[KNN - 1] = base + j + u;
#pragma unroll
                        for (int k = KNN - 1; k > 0; --k) {
                            if (bd[k] < bd[k - 1]) {
                                float td = bd[k]; bd[k] = bd[k - 1]; bd[k - 1] = td;
                                int   ti = bi[k]; bi[k] = bi[k - 1]; bi[k - 1] = ti;
                            }
                        }
                    }
                }
            }
        }
    }

    if (qa < H) {
#pragma unroll
        for (int k = 0; k < KNN; ++k) { g_ps[s][k][qa] = ad[k]; g_pi[s][k][qa] = ai[k]; }
    }
    if (qb < N) {
#pragma unroll
        for (int k = 0; k < KNN; ++k) { g_ps[s][k][qb] = bd[k]; g_pi[s][k][qb] = bi[k]; }
    }
}

// Phase 2: merge SPLIT partial lists (64 candidates) + IDW epilogue.
__global__ void __launch_bounds__(256) knn_merge_kernel(
    const float* __restrict__ qpts,
    const float* __restrict__ flow,
    float* __restrict__ out, int N)
{
    int qi = blockIdx.x * blockDim.x + threadIdx.x;
    if (qi >= N) return;

    float bd[KNN];
    int   bi[KNN];
#pragma unroll
    for (int k = 0; k < KNN; ++k) { bd[k] = CUDART_INF_F; bi[k] = 0; }

#pragma unroll
    for (int s = 0; s < SPLIT; ++s) {
#pragma unroll
        for (int k = 0; k < KNN; ++k) {
            float v = g_ps[s][k][qi];
            if (v < bd[KNN - 1]) {
                bd[KNN - 1] = v;
                bi[KNN - 1] = g_pi[s][k][qi];
#pragma unroll
                for (int t = KNN - 1; t > 0; --t) {
                    if (bd[t] < bd[t - 1]) {
                        float td = bd[t]; bd[t] = bd[t - 1]; bd[t - 1] = td;
                        int   ti = bi[t]; bi[t] = bi[t - 1]; bi[t - 1] = ti;
                    }
                }
            }
        }
    }

    float qx = qpts[3 * qi + 0];
    float qy = qpts[3 * qi + 1];
    float qz = qpts[3 * qi + 2];
    float q2 = fmaf(qx, qx, fmaf(qy, qy, qz * qz));

    float wsum = 0.f, ox = 0.f, oy = 0.f, oz = 0.f;
#pragma unroll
    for (int k = 0; k < KNN; ++k) {
        float d2 = fmaxf(q2 + bd[k], 0.0f);
        float w = 1.0f / (d2 + 1e-8f);
        int id = bi[k];
        ox = fmaf(w, flow[3 * id + 0], ox);
        oy = fmaf(w, flow[3 * id + 1], oy);
        oz = fmaf(w, flow[3 * id + 2], oz);
        wsum += w;
    }
    float inv = 1.0f / wsum;
    out[3 * qi + 0] = ox * inv;
    out[3 * qi + 1] = oy * inv;
    out[3 * qi + 2] = oz * inv;
}

extern "C" void kernel_launch(void* const* d_in, const int* in_sizes, int n_in,
                              void* d_out, int out_size) {
    const float* q = (const float*)d_in[0];
    const float* r = (const float*)d_in[1];
    const float* f = (const float*)d_in[2];
    int N = in_sizes[0] / 3;
    int M = in_sizes[1] / 3;
    if (M > MMAX) M = MMAX;
    if (N > NMAX) N = NMAX;
    int H = (N + 1) / 2;   // thread t owns queries t and t+H

    prep_refs_kernel<<<(M + 255) / 256, 256>>>(r, M);
    dim3 grid1((H + 255) / 256, SPLIT);
    knn_partial_kernel<<<grid1, 256>>>(q, N, M, H);
    knn_merge_kernel<<<(N + 255) / 256, 256>>>(q, f, (float*)d_out, N);
}

// round 4
// speedup vs baseline: 1.4482x; 1.4482x over previous
#include <cuda_runtime.h>
#include <math_constants.h>

// Inputs: query_points [N,3] f32, ref_points [M,3] f32, ref_flow [M,3] f32 ; out [N,3] f32
// Shape: N=32768, M=16384 (general up to bounds below).

#define NMAX  32768
#define MMAX  16384
#define TILE  2048          // 32 KB of float4 per tile
#define KNN   8
#define SPLIT 4             // M-dimension split: 128x4 = 512 blocks = single wave

__device__ float4 g_refs[MMAX];
__device__ float g_ps[SPLIT][KNN][NMAX];
__device__ int   g_pi[SPLIT][KNN][NMAX];

__global__ void prep_refs_kernel(const float* __restrict__ ref, int M) {
    int i = blockIdx.x * blockDim.x + threadIdx.x;
    if (i < M) {
        float x = ref[3 * i + 0];
        float y = ref[3 * i + 1];
        float z = ref[3 * i + 2];
        g_refs[i] = make_float4(x, y, z, fmaf(x, x, fmaf(y, y, z * z)));
    }
}

// Phase 1: one query per thread; each block scans one M-slice of 4096 candidates.
// score = |r|^2 - 2 q.r  (monotone in squared distance; |q|^2 added in phase 2).
__global__ void __launch_bounds__(256) knn_partial_kernel(
    const float* __restrict__ qpts, int N, int M)
{
    __shared__ float4 s_ref[TILE];

    const int qi = blockIdx.x * blockDim.x + threadIdx.x;
    const int s  = blockIdx.y;
    const int Ms = (M + SPLIT - 1) / SPLIT;
    const int lo = s * Ms;
    const int hi = min(lo + Ms, M);

    float qx = 0.f, qy = 0.f, qz = 0.f;
    if (qi < N) {
        qx = qpts[3 * qi + 0];
        qy = qpts[3 * qi + 1];
        qz = qpts[3 * qi + 2];
    }
    const float nqx = -2.0f * qx;
    const float nqy = -2.0f * qy;
    const float nqz = -2.0f * qz;

    float bd[KNN];
    int   bi[KNN];
#pragma unroll
    for (int k = 0; k < KNN; ++k) { bd[k] = CUDART_INF_F; bi[k] = 0; }

    for (int base = lo; base < hi; base += TILE) {
        int cnt = min(TILE, hi - base);
        __syncthreads();
        for (int j = threadIdx.x; j < TILE; j += blockDim.x) {
            s_ref[j] = (j < cnt) ? g_refs[base + j]
                                 : make_float4(0.f, 0.f, 0.f, CUDART_INF_F);
        }
        __syncthreads();

#pragma unroll 2
        for (int j = 0; j < TILE; j += 4) {
            float4 r0 = s_ref[j + 0];
            float4 r1 = s_ref[j + 1];
            float4 r2 = s_ref[j + 2];
            float4 r3 = s_ref[j + 3];
            float s0 = fmaf(r0.x, nqx, fmaf(r0.y, nqy, fmaf(r0.z, nqz, r0.w)));
            float s1 = fmaf(r1.x, nqx, fmaf(r1.y, nqy, fmaf(r1.z, nqz, r1.w)));
            float s2 = fmaf(r2.x, nqx, fmaf(r2.y, nqy, fmaf(r2.z, nqz, r2.w)));
            float s3 = fmaf(r3.x, nqx, fmaf(r3.y, nqy, fmaf(r3.z, nqz, r3.w)));
            float m = fminf(fminf(s0, s1), fminf(s2, s3));
            if (m < bd[KNN - 1]) {
                float sv[4] = {s0, s1, s2, s3};
#pragma unroll
                for (int u = 0; u < 4; ++u) {
                    if (sv[u] < bd[KNN - 1]) {
                        bd[KNN - 1] = sv[u];
                        bi[KNN - 1] = base + j + u;
#pragma unroll
                        for (int k = KNN - 1; k > 0; --k) {
                            if (bd[k] < bd[k - 1]) {
                                float td = bd[k]; bd[k] = bd[k - 1]; bd[k - 1] = td;
                                int   ti = bi[k]; bi[k] = bi[k - 1]; bi[k - 1] = ti;
                            }
                        }
                    }
                }
            }
        }
    }

    if (qi < N) {
#pragma unroll
        for (int k = 0; k < KNN; ++k) {
            g_ps[s][k][qi] = bd[k];
            g_pi[s][k][qi] = bi[k];
        }
    }
}

// Phase 2: merge SPLIT partial lists (SPLIT*KNN = 32 candidates) + IDW epilogue.
__global__ void __launch_bounds__(256) knn_merge_kernel(
    const float* __restrict__ qpts,
    const float* __restrict__ flow,
    float* __restrict__ out, int N)
{
    int qi = blockIdx.x * blockDim.x + threadIdx.x;
    if (qi >= N) return;

    float bd[KNN];
    int   bi[KNN];
#pragma unroll
    for (int k = 0; k < KNN; ++k) { bd[k] = CUDART_INF_F; bi[k] = 0; }

#pragma unroll
    for (int s = 0; s < SPLIT; ++s) {
#pragma unroll
        for (int k = 0; k < KNN; ++k) {
            float v = g_ps[s][k][qi];
            if (v < bd[KNN - 1]) {
                bd[KNN - 1] = v;
                bi[KNN - 1] = g_pi[s][k][qi];
#pragma unroll
                for (int t = KNN - 1; t > 0; --t) {
                    if (bd[t] < bd[t - 1]) {
                        float td = bd[t]; bd[t] = bd[t - 1]; bd[t - 1] = td;
                        int   ti = bi[t]; bi[t] = bi[t - 1]; bi[t - 1] = ti;
                    }
                }
            }
        }
    }

    float qx = qpts[3 * qi + 0];
    float qy = qpts[3 * qi + 1];
    float qz = qpts[3 * qi + 2];
    float q2 = fmaf(qx, qx, fmaf(qy, qy, qz * qz));

    float wsum = 0.f, ox = 0.f, oy = 0.f, oz = 0.f;
#pragma unroll
    for (int k = 0; k < KNN; ++k) {
        float d2 = fmaxf(q2 + bd[k], 0.0f);
        float w = 1.0f / (d2 + 1e-8f);
        int id = bi[k];
        ox = fmaf(w, flow[3 * id + 0], ox);
        oy = fmaf(w, flow[3 * id + 1], oy);
        oz = fmaf(w, flow[3 * id + 2], oz);
        wsum += w;
    }
    float inv = 1.0f / wsum;
    out[3 * qi + 0] = ox * inv;
    out[3 * qi + 1] = oy * inv;
    out[3 * qi + 2] = oz * inv;
}

extern "C" void kernel_launch(void* const* d_in, const int* in_sizes, int n_in,
                              void* d_out, int out_size) {
    const float* q = (const float*)d_in[0];
    const float* r = (const float*)d_in[1];
    const float* f = (const float*)d_in[2];
    int N = in_sizes[0] / 3;
    int M = in_sizes[1] / 3;
    if (M > MMAX) M = MMAX;
    if (N > NMAX) N = NMAX;

    prep_refs_kernel<<<(M + 255) / 256, 256>>>(r, M);
    dim3 grid1((N + 255) / 256, SPLIT);
    knn_partial_kernel<<<grid1, 256>>>(q, N, M);
    knn_merge_kernel<<<(N + 255) / 256, 256>>>(q, f, (float*)d_out, N);
}

// round 5
// speedup vs baseline: 1.5804x; 1.0913x over previous
#include <cuda_runtime.h>
#include <math_constants.h>

// Exact 8-NN IDW flow interpolation via uniform grid + expanding-shell search.
// Inputs: query_points [N,3] f32, ref_points [M,3] f32, ref_flow [M,3] f32 ; out [N,3] f32

#define NMAX  32768
#define MMAX  16384
#define KNN   8
#define G     32
#define NCELL (G * G * G)

__device__ float4 g_pts[MMAX];        // grid-sorted refs: (x, y, z, |r|^2)
__device__ int    g_sid[MMAX];        // grid-sorted -> original index
__device__ int    g_cstart[NCELL + 1];
__device__ int    g_ccnt[NCELL];
__device__ int    g_ccur[NCELL];
__device__ int    g_cellof[MMAX];
__device__ float  g_bb[8];            // [0..2]=min, [3..5]=1/h per axis, [6]=hmin

__global__ void zero_cells_kernel() {
    int i = blockIdx.x * blockDim.x + threadIdx.x;
    if (i < NCELL) g_ccnt[i] = 0;
}

// Single-block bbox reduction over refs, then derive cell sizes.
__global__ void bbox_kernel(const float* __restrict__ ref, int M) {
    __shared__ float smn[3][256], smx[3][256];
    int t = threadIdx.x;
    float mn[3] = {CUDART_INF_F, CUDART_INF_F, CUDART_INF_F};
    float mx[3] = {-CUDART_INF_F, -CUDART_INF_F, -CUDART_INF_F};
    for (int i = t; i < M; i += 256) {
#pragma unroll
        for (int a = 0; a < 3; ++a) {
            float v = ref[3 * i + a];
            mn[a] = fminf(mn[a], v);
            mx[a] = fmaxf(mx[a], v);
        }
    }
#pragma unroll
    for (int a = 0; a < 3; ++a) { smn[a][t] = mn[a]; smx[a][t] = mx[a]; }
    __syncthreads();
    for (int off = 128; off > 0; off >>= 1) {
        if (t < off) {
#pragma unroll
            for (int a = 0; a < 3; ++a) {
                smn[a][t] = fminf(smn[a][t], smn[a][t + off]);
                smx[a][t] = fmaxf(smx[a][t], smx[a][t + off]);
            }
        }
        __syncthreads();
    }
    if (t == 0) {
        float hmin = CUDART_INF_F;
#pragma unroll
        for (int a = 0; a < 3; ++a) {
            float lo = smn[a][0] - 1e-4f;
            float hi = smx[a][0] + 1e-4f;
            float h = fmaxf((hi - lo) / (float)G, 1e-6f);
            g_bb[a] = lo;
            g_bb[3 + a] = 1.0f / h;
            hmin = fminf(hmin, h);
        }
        g_bb[6] = hmin;
    }
}

__device__ __forceinline__ int cell_of(float x, float y, float z) {
    int cx = (int)((x - g_bb[0]) * g_bb[3]);
    int cy = (int)((y - g_bb[1]) * g_bb[4]);
    int cz = (int)((z - g_bb[2]) * g_bb[5]);
    cx = min(G - 1, max(0, cx));
    cy = min(G - 1, max(0, cy));
    cz = min(G - 1, max(0, cz));
    return (cz * G + cy) * G + cx;
}

__global__ void hist_kernel(const float* __restrict__ ref, int M) {
    int i = blockIdx.x * blockDim.x + threadIdx.x;
    if (i < M) {
        int c = cell_of(ref[3 * i + 0], ref[3 * i + 1], ref[3 * i + 2]);
        g_cellof[i] = c;
        atomicAdd(&g_ccnt[c], 1);
    }
}

// Exclusive scan of 32768 cell counts: 1024 threads x 32 cells each.
__global__ void scan_kernel(int M) {
    __shared__ int ssum[1024];
    int t = threadIdx.x;
    int base = t * (NCELL / 1024);
    int s = 0;
    for (int i = 0; i < NCELL / 1024; ++i) s += g_ccnt[base + i];
    ssum[t] = s;
    __syncthreads();
    int v = s;
    for (int off = 1; off < 1024; off <<= 1) {
        int u = (t >= off) ? ssum[t - off] : 0;
        __syncthreads();
        v += u;
        ssum[t] = v;
        __syncthreads();
    }
    int run = v - s;  // exclusive prefix for this thread's chunk
    for (int i = 0; i < NCELL / 1024; ++i) {
        g_cstart[base + i] = run;
        g_ccur[base + i] = run;
        run += g_ccnt[base + i];
    }
    if (t == 1023) g_cstart[NCELL] = M;
}

__global__ void scatter_kernel(const float* __restrict__ ref, int M) {
    int i = blockIdx.x * blockDim.x + threadIdx.x;
    if (i < M) {
        float x = ref[3 * i + 0];
        float y = ref[3 * i + 1];
        float z = ref[3 * i + 2];
        int c = g_cellof[i];
        int p = atomicAdd(&g_ccur[c], 1);
        g_pts[p] = make_float4(x, y, z, fmaf(x, x, fmaf(y, y, z * z)));
        g_sid[p] = i;
    }
}

// Exact KNN via expanding Chebyshev shells + IDW epilogue.
// score = |r|^2 - 2 q.r  (same formula as reference, monotone in d^2).
__global__ void __launch_bounds__(128) knn_grid_kernel(
    const float* __restrict__ qpts,
    const float* __restrict__ flow,
    float* __restrict__ out, int N)
{
    int qi = blockIdx.x * blockDim.x + threadIdx.x;
    if (qi >= N) return;

    const float qx = qpts[3 * qi + 0];
    const float qy = qpts[3 * qi + 1];
    const float qz = qpts[3 * qi + 2];
    const float nqx = -2.0f * qx;
    const float nqy = -2.0f * qy;
    const float nqz = -2.0f * qz;
    const float q2 = fmaf(qx, qx, fmaf(qy, qy, qz * qz));
    const float hmin = g_bb[6];

    int cx = (int)((qx - g_bb[0]) * g_bb[3]);
    int cy = (int)((qy - g_bb[1]) * g_bb[4]);
    int cz = (int)((qz - g_bb[2]) * g_bb[5]);
    cx = min(G - 1, max(0, cx));
    cy = min(G - 1, max(0, cy));
    cz = min(G - 1, max(0, cz));

    float bd[KNN];
    int   bi[KNN];
#pragma unroll
    for (int k = 0; k < KNN; ++k) { bd[k] = CUDART_INF_F; bi[k] = 0; }

    // Scan one contiguous x-run of cells in row (z, y): cells [x0, x1].
    auto do_row = [&](int z, int y, int x0, int x1) {
        if ((unsigned)z >= G || (unsigned)y >= G) return;
        x0 = max(x0, 0);
        x1 = min(x1, G - 1);
        if (x0 > x1) return;
        int rb = (z * G + y) * G;
        int s = g_cstart[rb + x0];
        int e = g_cstart[rb + x1 + 1];
        for (int p = s; p < e; ++p) {
            float4 r = g_pts[p];
            float sc = fmaf(r.x, nqx, fmaf(r.y, nqy, fmaf(r.z, nqz, r.w)));
            if (sc < bd[KNN - 1]) {
                bd[KNN - 1] = sc;
                bi[KNN - 1] = g_sid[p];
#pragma unroll
                for (int k = KNN - 1; k > 0; --k) {
                    if (bd[k] < bd[k - 1]) {
                        float td = bd[k]; bd[k] = bd[k - 1]; bd[k - 1] = td;
                        int   ti = bi[k]; bi[k] = bi[k - 1]; bi[k - 1] = ti;
                    }
                }
            }
        }
    };

    for (int l = 0; l < G; ++l) {
        if (l == 0) {
            do_row(cz, cy, cx, cx);
        } else {
            // z = +/- l full faces
            for (int y = cy - l; y <= cy + l; ++y) {
                do_row(cz - l, y, cx - l, cx + l);
                do_row(cz + l, y, cx - l, cx + l);
            }
            // z interior
            for (int z = cz - l + 1; z <= cz + l - 1; ++z) {
                do_row(z, cy - l, cx - l, cx + l);
                do_row(z, cy + l, cx - l, cx + l);
                for (int y = cy - l + 1; y <= cy + l - 1; ++y) {
                    do_row(z, y, cx - l, cx - l);
                    do_row(z, y, cx + l, cx + l);
                }
            }
        }
        // Remaining rings have true d^2 >= (l*hmin)^2 (convex projection covers
        // out-of-bbox queries). 0.05 margin covers fp cancellation in the score.
        float bound = (float)l * hmin;
        if (q2 + bd[KNN - 1] < bound * bound - 0.05f) break;
    }

    // IDW with POWER=2: w = 1 / (max(d2,0) + 1e-8); d2 = |q|^2 + score.
    float wsum = 0.f, ox = 0.f, oy = 0.f, oz = 0.f;
#pragma unroll
    for (int k = 0; k < KNN; ++k) {
        float d2 = fmaxf(q2 + bd[k], 0.0f);
        float w = 1.0f / (d2 + 1e-8f);
        int id = bi[k];
        ox = fmaf(w, flow[3 * id + 0], ox);
        oy = fmaf(w, flow[3 * id + 1], oy);
        oz = fmaf(w, flow[3 * id + 2], oz);
        wsum += w;
    }
    float inv = 1.0f / wsum;
    out[3 * qi + 0] = ox * inv;
    out[3 * qi + 1] = oy * inv;
    out[3 * qi + 2] = oz * inv;
}

extern "C" void kernel_launch(void* const* d_in, const int* in_sizes, int n_in,
                              void* d_out, int out_size) {
    const float* q = (const float*)d_in[0];
    const float* r = (const float*)d_in[1];
    const float* f = (const float*)d_in[2];
    int N = in_sizes[0] / 3;
    int M = in_sizes[1] / 3;
    if (M > MMAX) M = MMAX;
    if (N > NMAX) N = NMAX;

    zero_cells_kernel<<<NCELL / 256, 256>>>();
    bbox_kernel<<<1, 256>>>(r, M);
    hist_kernel<<<(M + 255) / 256, 256>>>(r, M);
    scan_kernel<<<1, 1024>>>(M);
    scatter_kernel<<<(M + 255) / 256, 256>>>(r, M);
    knn_grid_kernel<<<(N + 127) / 128, 128>>>(q, f, (float*)d_out, N);
}

// round 6
// speedup vs baseline: 1.7606x; 1.1140x over previous
#include <cuda_runtime.h>
#include <math_constants.h>

// Exact 8-NN IDW flow interpolation via uniform grid + expanding-shell search,
// with queries counting-sorted by cell for warp coherence.
// Inputs: query_points [N,3] f32, ref_points [M,3] f32, ref_flow [M,3] f32 ; out [N,3] f32

#define NMAX  32768
#define MMAX  16384
#define KNN   8
#define G     32
#define NCELL (G * G * G)

__device__ float4 g_pts[MMAX];         // grid-sorted refs: (x, y, z, |r|^2)
__device__ int    g_sid[MMAX];         // grid-sorted -> original ref index
__device__ int    g_cstart[NCELL + 1];
__device__ int    g_ccnt[NCELL];
__device__ int    g_ccur[NCELL];
__device__ int    g_cellof[MMAX];
__device__ int    g_qcnt[NCELL];
__device__ int    g_qcur[NCELL];
__device__ int    g_qstart[NCELL + 1];
__device__ int    g_qcell[NMAX];
__device__ int    g_qid[NMAX];         // sorted order -> original query index
__device__ float  g_bb[8];             // [0..2]=min, [3..5]=1/h, [6]=hmin

__global__ void zero_cells_kernel() {
    int i = blockIdx.x * blockDim.x + threadIdx.x;
    if (i < NCELL) { g_ccnt[i] = 0; g_qcnt[i] = 0; }
}

__global__ void bbox_kernel(const float* __restrict__ ref, int M) {
    __shared__ float smn[3][256], smx[3][256];
    int t = threadIdx.x;
    float mn[3] = {CUDART_INF_F, CUDART_INF_F, CUDART_INF_F};
    float mx[3] = {-CUDART_INF_F, -CUDART_INF_F, -CUDART_INF_F};
    for (int i = t; i < M; i += 256) {
#pragma unroll
        for (int a = 0; a < 3; ++a) {
            float v = ref[3 * i + a];
            mn[a] = fminf(mn[a], v);
            mx[a] = fmaxf(mx[a], v);
        }
    }
#pragma unroll
    for (int a = 0; a < 3; ++a) { smn[a][t] = mn[a]; smx[a][t] = mx[a]; }
    __syncthreads();
    for (int off = 128; off > 0; off >>= 1) {
        if (t < off) {
#pragma unroll
            for (int a = 0; a < 3; ++a) {
                smn[a][t] = fminf(smn[a][t], smn[a][t + off]);
                smx[a][t] = fmaxf(smx[a][t], smx[a][t + off]);
            }
        }
        __syncthreads();
    }
    if (t == 0) {
        float hmin = CUDART_INF_F;
#pragma unroll
        for (int a = 0; a < 3; ++a) {
            float lo = smn[a][0] - 1e-4f;
            float hi = smx[a][0] + 1e-4f;
            float h = fmaxf((hi - lo) / (float)G, 1e-6f);
            g_bb[a] = lo;
            g_bb[3 + a] = 1.0f / h;
            hmin = fminf(hmin, h);
        }
        g_bb[6] = hmin;
    }
}

__device__ __forceinline__ int cell_of(float x, float y, float z) {
    int cx = (int)((x - g_bb[0]) * g_bb[3]);
    int cy = (int)((y - g_bb[1]) * g_bb[4]);
    int cz = (int)((z - g_bb[2]) * g_bb[5]);
    cx = min(G - 1, max(0, cx));
    cy = min(G - 1, max(0, cy));
    cz = min(G - 1, max(0, cz));
    return (cz * G + cy) * G + cx;
}

// Histogram refs AND queries in one launch (i < M: refs; else: queries).
__global__ void hist_kernel(const float* __restrict__ ref,
                            const float* __restrict__ qp, int M, int N) {
    int i = blockIdx.x * blockDim.x + threadIdx.x;
    if (i < M) {
        int c = cell_of(ref[3 * i + 0], ref[3 * i + 1], ref[3 * i + 2]);
        g_cellof[i] = c;
        atomicAdd(&g_ccnt[c], 1);
    } else if (i < M + N) {
        int j = i - M;
        int c = cell_of(qp[3 * j + 0], qp[3 * j + 1], qp[3 * j + 2]);
        g_qcell[j] = c;
        atomicAdd(&g_qcnt[c], 1);
    }
}

// Two-level shfl scan: 1024 threads x 32 cells each. grid=2: block 0 scans
// ref-cell counts, block 1 scans query-cell counts.
__global__ void __launch_bounds__(1024) scan_kernel(int M, int N) {
    int* cnt   = blockIdx.x ? g_qcnt   : g_ccnt;
    int* start = blockIdx.x ? g_qstart : g_cstart;
    int* cur   = blockIdx.x ? g_qcur   : g_ccur;
    int  tot   = blockIdx.x ? N : M;
    const int C = NCELL / 1024;

    __shared__ int wsum[32];
    int t = threadIdx.x;
    int lane = t & 31, wid = t >> 5;
    int base = t * C;

    int s = 0;
#pragma unroll 8
    for (int i = 0; i < C; ++i) s += cnt[base + i];

    int v = s;
#pragma unroll
    for (int off = 1; off < 32; off <<= 1) {
        int u = __shfl_up_sync(0xffffffffu, v, off);
        if (lane >= off) v += u;
    }
    if (lane == 31) wsum[wid] = v;
    __syncthreads();
    if (wid == 0) {
        int w = wsum[lane];
#pragma unroll
        for (int off = 1; off < 32; off <<= 1) {
            int u = __shfl_up_sync(0xffffffffu, w, off);
            if (lane >= off) w += u;
        }
        wsum[lane] = w;
    }
    __syncthreads();
    int run = v - s + (wid ? wsum[wid - 1] : 0);  // exclusive prefix
#pragma unroll 8
    for (int i = 0; i < C; ++i) {
        start[base + i] = run;
        cur[base + i] = run;
        run += cnt[base + i];
    }
    if (t == 1023) start[NCELL] = tot;
}

// Scatter refs (packed float4 + id) AND query ids in one launch.
__global__ void scatter_kernel(const float* __restrict__ ref, int M, int N) {
    int i = blockIdx.x * blockDim.x + threadIdx.x;
    if (i < M) {
        float x = ref[3 * i + 0];
        float y = ref[3 * i + 1];
        float z = ref[3 * i + 2];
        int c = g_cellof[i];
        int p = atomicAdd(&g_ccur[c], 1);
        g_pts[p] = make_float4(x, y, z, fmaf(x, x, fmaf(y, y, z * z)));
        g_sid[p] = i;
    } else if (i < M + N) {
        int j = i - M;
        int c = g_qcell[j];
        int p = atomicAdd(&g_qcur[c], 1);
        g_qid[p] = j;
    }
}

// Exact KNN via expanding Chebyshev shells + IDW. Threads walk cell-sorted
// query order, so warp lanes share cells/shells.
__global__ void __launch_bounds__(128) knn_grid_kernel(
    const float* __restrict__ qpts,
    const float* __restrict__ flow,
    float* __restrict__ out, int N)
{
    int tq = blockIdx.x * blockDim.x + threadIdx.x;
    if (tq >= N) return;
    int qi = g_qid[tq];

    const float qx = qpts[3 * qi + 0];
    const float qy = qpts[3 * qi + 1];
    const float qz = qpts[3 * qi + 2];
    const float nqx = -2.0f * qx;
    const float nqy = -2.0f * qy;
    const float nqz = -2.0f * qz;
    const float q2 = fmaf(qx, qx, fmaf(qy, qy, qz * qz));
    const float hmin = g_bb[6];

    int cx = (int)((qx - g_bb[0]) * g_bb[3]);
    int cy = (int)((qy - g_bb[1]) * g_bb[4]);
    int cz = (int)((qz - g_bb[2]) * g_bb[5]);
    cx = min(G - 1, max(0, cx));
    cy = min(G - 1, max(0, cy));
    cz = min(G - 1, max(0, cz));

    float bd[KNN];
    int   bi[KNN];
#pragma unroll
    for (int k = 0; k < KNN; ++k) { bd[k] = CUDART_INF_F; bi[k] = 0; }

    auto do_row = [&](int z, int y, int x0, int x1) {
        if ((unsigned)z >= G || (unsigned)y >= G) return;
        x0 = max(x0, 0);
        x1 = min(x1, G - 1);
        if (x0 > x1) return;
        int rb = (z * G + y) * G;
        int s = g_cstart[rb + x0];
        int e = g_cstart[rb + x1 + 1];
        for (int p = s; p < e; ++p) {
            float4 r = g_pts[p];
            float sc = fmaf(r.x, nqx, fmaf(r.y, nqy, fmaf(r.z, nqz, r.w)));
            if (sc < bd[KNN - 1]) {
                bd[KNN - 1] = sc;
                bi[KNN - 1] = g_sid[p];
#pragma unroll
                for (int k = KNN - 1; k > 0; --k) {
                    if (bd[k] < bd[k - 1]) {
                        float td = bd[k]; bd[k] = bd[k - 1]; bd[k - 1] = td;
                        int   ti = bi[k]; bi[k] = bi[k - 1]; bi[k - 1] = ti;
                    }
                }
            }
        }
    };

    for (int l = 0; l < G; ++l) {
        if (l == 0) {
            do_row(cz, cy, cx, cx);
        } else {
            for (int y = cy - l; y <= cy + l; ++y) {
                do_row(cz - l, y, cx - l, cx + l);
                do_row(cz + l, y, cx - l, cx + l);
            }
            for (int z = cz - l + 1; z <= cz + l - 1; ++z) {
                do_row(z, cy - l, cx - l, cx + l);
                do_row(z, cy + l, cx - l, cx + l);
                for (int y = cy - l + 1; y <= cy + l - 1; ++y) {
                    do_row(z, y, cx - l, cx - l);
                    do_row(z, y, cx + l, cx + l);
                }
            }
        }
        // Remaining rings have true d^2 >= (l*hmin)^2 (convex projection covers
        // out-of-bbox queries). 0.05 margin covers fp cancellation in the score.
        float bound = (float)l * hmin;
        if (q2 + bd[KNN - 1] < bound * bound - 0.05f) break;
    }

    // IDW with POWER=2: w = 1 / (max(d2,0) + 1e-8); d2 = |q|^2 + score.
    float wsum = 0.f, ox = 0.f, oy = 0.f, oz = 0.f;
#pragma unroll
    for (int k = 0; k < KNN; ++k) {
        float d2 = fmaxf(q2 + bd[k], 0.0f);
        float w = 1.0f / (d2 + 1e-8f);
        int id = bi[k];
        ox = fmaf(w, flow[3 * id + 0], ox);
        oy = fmaf(w, flow[3 * id + 1], oy);
        oz = fmaf(w, flow[3 * id + 2], oz);
        wsum += w;
    }
    float inv = 1.0f / wsum;
    out[3 * qi + 0] = ox * inv;
    out[3 * qi + 1] = oy * inv;
    out[3 * qi + 2] = oz * inv;
}

extern "C" void kernel_launch(void* const* d_in, const int* in_sizes, int n_in,
                              void* d_out, int out_size) {
    const float* q = (const float*)d_in[0];
    const float* r = (const float*)d_in[1];
    const float* f = (const float*)d_in[2];
    int N = in_sizes[0] / 3;
    int M = in_sizes[1] / 3;
    if (M > MMAX) M = MMAX;
    if (N > NMAX) N = NMAX;

    zero_cells_kernel<<<NCELL / 256, 256>>>();
    bbox_kernel<<<1, 256>>>(r, M);
    hist_kernel<<<(M + N + 255) / 256, 256>>>(r, q, M, N);
    scan_kernel<<<2, 1024>>>(M, N);
    scatter_kernel<<<(M + N + 255) / 256, 256>>>(r, M, N);
    knn_grid_kernel<<<(N + 127) / 128, 128>>>(q, f, (float*)d_out, N);
}

// round 7
// speedup vs baseline: 1.8466x; 1.0488x over previous
#include <cuda_runtime.h>
#include <math_constants.h>

// Exact 8-NN IDW flow interpolation: uniform grid + expanding shells.
// Phase A: per-thread search limited to shells l<=2 (handles ~96% of queries).
// Phase B: warp-cooperative search for the heavy-tail queries.
// Inputs: query_points [N,3] f32, ref_points [M,3] f32, ref_flow [M,3] f32 ; out [N,3] f32

#define NMAX  32768
#define MMAX  16384
#define KNN   8
#define G     32
#define NCELL (G * G * G)
#define LMAXA 2

__device__ float4 g_pts[MMAX];
__device__ int    g_sid[MMAX];
__device__ int    g_cstart[NCELL + 1];
__device__ int    g_ccnt[NCELL];
__device__ int    g_ccur[NCELL];
__device__ int    g_cellof[MMAX];
__device__ int    g_qcnt[NCELL];
__device__ int    g_qcur[NCELL];
__device__ int    g_qstart[NCELL + 1];
__device__ int    g_qcell[NMAX];
__device__ int    g_qid[NMAX];
__device__ int    g_hard[NMAX];
__device__ int    g_hardcnt;
__device__ float  g_bb[8];   // [0..2]=min, [3..5]=1/h, [6]=hmin

__global__ void zero_cells_kernel() {
    int i = blockIdx.x * blockDim.x + threadIdx.x;
    if (i < NCELL) { g_ccnt[i] = 0; g_qcnt[i] = 0; }
    if (i == 0) g_hardcnt = 0;
}

__global__ void bbox_kernel(const float* __restrict__ ref, int M) {
    __shared__ float smn[3][256], smx[3][256];
    int t = threadIdx.x;
    float mn[3] = {CUDART_INF_F, CUDART_INF_F, CUDART_INF_F};
    float mx[3] = {-CUDART_INF_F, -CUDART_INF_F, -CUDART_INF_F};
    for (int i = t; i < M; i += 256) {
#pragma unroll
        for (int a = 0; a < 3; ++a) {
            float v = ref[3 * i + a];
            mn[a] = fminf(mn[a], v);
            mx[a] = fmaxf(mx[a], v);
        }
    }
#pragma unroll
    for (int a = 0; a < 3; ++a) { smn[a][t] = mn[a]; smx[a][t] = mx[a]; }
    __syncthreads();
    for (int off = 128; off > 0; off >>= 1) {
        if (t < off) {
#pragma unroll
            for (int a = 0; a < 3; ++a) {
                smn[a][t] = fminf(smn[a][t], smn[a][t + off]);
                smx[a][t] = fmaxf(smx[a][t], smx[a][t + off]);
            }
        }
        __syncthreads();
    }
    if (t == 0) {
        float hmin = CUDART_INF_F;
#pragma unroll
        for (int a = 0; a < 3; ++a) {
            float lo = smn[a][0] - 1e-4f;
            float hi = smx[a][0] + 1e-4f;
            float h = fmaxf((hi - lo) / (float)G, 1e-6f);
            g_bb[a] = lo;
            g_bb[3 + a] = 1.0f / h;
            hmin = fminf(hmin, h);
        }
        g_bb[6] = hmin;
    }
}

__device__ __forceinline__ int cell_of(float x, float y, float z) {
    int cx = (int)((x - g_bb[0]) * g_bb[3]);
    int cy = (int)((y - g_bb[1]) * g_bb[4]);
    int cz = (int)((z - g_bb[2]) * g_bb[5]);
    cx = min(G - 1, max(0, cx));
    cy = min(G - 1, max(0, cy));
    cz = min(G - 1, max(0, cz));
    return (cz * G + cy) * G + cx;
}

__global__ void hist_kernel(const float* __restrict__ ref,
                            const float* __restrict__ qp, int M, int N) {
    int i = blockIdx.x * blockDim.x + threadIdx.x;
    if (i < M) {
        int c = cell_of(ref[3 * i + 0], ref[3 * i + 1], ref[3 * i + 2]);
        g_cellof[i] = c;
        atomicAdd(&g_ccnt[c], 1);
    } else if (i < M + N) {
        int j = i - M;
        int c = cell_of(qp[3 * j + 0], qp[3 * j + 1], qp[3 * j + 2]);
        g_qcell[j] = c;
        atomicAdd(&g_qcnt[c], 1);
    }
}

__global__ void __launch_bounds__(1024) scan_kernel(int M, int N) {
    int* cnt   = blockIdx.x ? g_qcnt   : g_ccnt;
    int* start = blockIdx.x ? g_qstart : g_cstart;
    int* cur   = blockIdx.x ? g_qcur   : g_ccur;
    int  tot   = blockIdx.x ? N : M;
    const int C = NCELL / 1024;

    __shared__ int wsum[32];
    int t = threadIdx.x;
    int lane = t & 31, wid = t >> 5;
    int base = t * C;

    int s = 0;
#pragma unroll 8
    for (int i = 0; i < C; ++i) s += cnt[base + i];

    int v = s;
#pragma unroll
    for (int off = 1; off < 32; off <<= 1) {
        int u = __shfl_up_sync(0xffffffffu, v, off);
        if (lane >= off) v += u;
    }
    if (lane == 31) wsum[wid] = v;
    __syncthreads();
    if (wid == 0) {
        int w = wsum[lane];
#pragma unroll
        for (int off = 1; off < 32; off <<= 1) {
            int u = __shfl_up_sync(0xffffffffu, w, off);
            if (lane >= off) w += u;
        }
        wsum[lane] = w;
    }
    __syncthreads();
    int run = v - s + (wid ? wsum[wid - 1] : 0);
#pragma unroll 8
    for (int i = 0; i < C; ++i) {
        start[base + i] = run;
        cur[base + i] = run;
        run += cnt[base + i];
    }
    if (t == 1023) start[NCELL] = tot;
}

__global__ void scatter_kernel(const float* __restrict__ ref, int M, int N) {
    int i = blockIdx.x * blockDim.x + threadIdx.x;
    if (i < M) {
        float x = ref[3 * i + 0];
        float y = ref[3 * i + 1];
        float z = ref[3 * i + 2];
        int c = g_cellof[i];
        int p = atomicAdd(&g_ccur[c], 1);
        g_pts[p] = make_float4(x, y, z, fmaf(x, x, fmaf(y, y, z * z)));
        g_sid[p] = i;
    } else if (i < M + N) {
        int j = i - M;
        int c = g_qcell[j];
        int p = atomicAdd(&g_qcur[c], 1);
        g_qid[p] = j;
    }
}

__device__ __forceinline__ void idw_store(
    const float* __restrict__ flow, float* __restrict__ out,
    int qi, float q2, const float* bd, const int* bi)
{
    float wsum = 0.f, ox = 0.f, oy = 0.f, oz = 0.f;
#pragma unroll
    for (int k = 0; k < KNN; ++k) {
        float d2 = fmaxf(q2 + bd[k], 0.0f);
        float w = 1.0f / (d2 + 1e-8f);
        int id = bi[k];
        ox = fmaf(w, flow[3 * id + 0], ox);
        oy = fmaf(w, flow[3 * id + 1], oy);
        oz = fmaf(w, flow[3 * id + 2], oz);
        wsum += w;
    }
    float inv = 1.0f / wsum;
    out[3 * qi + 0] = ox * inv;
    out[3 * qi + 1] = oy * inv;
    out[3 * qi + 2] = oz * inv;
}

// Phase A: per-thread, shells l<=LMAXA. Unresolved queries go to the hard list.
__global__ void __launch_bounds__(128) knn_easy_kernel(
    const float* __restrict__ qpts,
    const float* __restrict__ flow,
    float* __restrict__ out, int N)
{
    int tq = blockIdx.x * blockDim.x + threadIdx.x;
    if (tq >= N) return;
    int qi = g_qid[tq];

    const float qx = qpts[3 * qi + 0];
    const float qy = qpts[3 * qi + 1];
    const float qz = qpts[3 * qi + 2];
    const float nqx = -2.0f * qx;
    const float nqy = -2.0f * qy;
    const float nqz = -2.0f * qz;
    const float q2 = fmaf(qx, qx, fmaf(qy, qy, qz * qz));
    const float hmin = g_bb[6];

    int cx = (int)((qx - g_bb[0]) * g_bb[3]);
    int cy = (int)((qy - g_bb[1]) * g_bb[4]);
    int cz = (int)((qz - g_bb[2]) * g_bb[5]);
    cx = min(G - 1, max(0, cx));
    cy = min(G - 1, max(0, cy));
    cz = min(G - 1, max(0, cz));

    float bd[KNN];
    int   bi[KNN];
#pragma unroll
    for (int k = 0; k < KNN; ++k) { bd[k] = CUDART_INF_F; bi[k] = 0; }

    auto do_row = [&](int z, int y, int x0, int x1) {
        if ((unsigned)z >= G || (unsigned)y >= G) return;
        x0 = max(x0, 0);
        x1 = min(x1, G - 1);
        if (x0 > x1) return;
        int rb = (z * G + y) * G;
        int s = g_cstart[rb + x0];
        int e = g_cstart[rb + x1 + 1];
        for (int p = s; p < e; ++p) {
            float4 r = g_pts[p];
            float sc = fmaf(r.x, nqx, fmaf(r.y, nqy, fmaf(r.z, nqz, r.w)));
            if (sc < bd[KNN - 1]) {
                bd[KNN - 1] = sc;
                bi[KNN - 1] = g_sid[p];
#pragma unroll
                for (int k = KNN - 1; k > 0; --k) {
                    if (bd[k] < bd[k - 1]) {
                        float td = bd[k]; bd[k] = bd[k - 1]; bd[k - 1] = td;
                        int   ti = bi[k]; bi[k] = bi[k - 1]; bi[k - 1] = ti;
                    }
                }
            }
        }
    };

    bool done = false;
    for (int l = 0; l <= LMAXA; ++l) {
        if (l == 0) {
            do_row(cz, cy, cx, cx);
        } else {
            for (int y = cy - l; y <= cy + l; ++y) {
                do_row(cz - l, y, cx - l, cx + l);
                do_row(cz + l, y, cx - l, cx + l);
            }
            for (int z = cz - l + 1; z <= cz + l - 1; ++z) {
                do_row(z, cy - l, cx - l, cx + l);
                do_row(z, cy + l, cx - l, cx + l);
                for (int y = cy - l + 1; y <= cy + l - 1; ++y) {
                    do_row(z, y, cx - l, cx - l);
                    do_row(z, y, cx + l, cx + l);
                }
            }
        }
        float bound = (float)l * hmin;
        if (q2 + bd[KNN - 1] < bound * bound - 0.05f) { done = true; break; }
    }

    if (done) {
        idw_store(flow, out, qi, q2, bd, bi);
    } else {
        int slot = atomicAdd(&g_hardcnt, 1);
        g_hard[slot] = qi;
    }
}

// Phase B: one warp per hard query. Lanes split (z,y) row-pairs of each shell;
// per-shell, lane 0 merges all lanes' top-8s (exact global top-8) for the stop
// bound; the final merge feeds IDW directly.
__global__ void __launch_bounds__(256) knn_hard_kernel(
    const float* __restrict__ qpts,
    const float* __restrict__ flow,
    float* __restrict__ out)
{
    __shared__ float sdist[8][32 * KNN];
    __shared__ int   sidx[8][32 * KNN];

    int lane = threadIdx.x & 31;
    int wslot = threadIdx.x >> 5;
    int wgid = (blockIdx.x * blockDim.x + threadIdx.x) >> 5;
    int nwarps = (gridDim.x * blockDim.x) >> 5;
    int hcnt = g_hardcnt;
    const float hmin = g_bb[6];

    for (int h = wgid; h < hcnt; h += nwarps) {
        int qi = g_hard[h];
        const float qx = qpts[3 * qi + 0];
        const float qy = qpts[3 * qi + 1];
        const float qz = qpts[3 * qi + 2];
        const float nqx = -2.0f * qx;
        const float nqy = -2.0f * qy;
        const float nqz = -2.0f * qz;
        const float q2 = fmaf(qx, qx, fmaf(qy, qy, qz * qz));

        int cx = (int)((qx - g_bb[0]) * g_bb[3]);
        int cy = (int)((qy - g_bb[1]) * g_bb[4]);
        int cz = (int)((qz - g_bb[2]) * g_bb[5]);
        cx = min(G - 1, max(0, cx));
        cy = min(G - 1, max(0, cy));
        cz = min(G - 1, max(0, cz));

        float bd[KNN];
        int   bi[KNN];
#pragma unroll
        for (int k = 0; k < KNN; ++k) { bd[k] = CUDART_INF_F; bi[k] = 0; }

        auto scan_run = [&](int z, int y, int x0, int x1) {
            if ((unsigned)z >= G || (unsigned)y >= G) return;
            x0 = max(x0, 0);
            x1 = min(x1, G - 1);
            if (x0 > x1) return;
            int rb = (z * G + y) * G;
            int s = g_cstart[rb + x0];
            int e = g_cstart[rb + x1 + 1];
            for (int p = s; p < e; ++p) {
                float4 r = g_pts[p];
                float sc = fmaf(r.x, nqx, fmaf(r.y, nqy, fmaf(r.z, nqz, r.w)));
                if (sc < bd[KNN - 1]) {
                    bd[KNN - 1] = sc;
                    bi[KNN - 1] = g_sid[p];
#pragma unroll
                    for (int k = KNN - 1; k > 0; --k) {
                        if (bd[k] < bd[k - 1]) {
                            float td = bd[k]; bd[k] = bd[k - 1]; bd[k - 1] = td;
                            int   ti = bi[k]; bi[k] = bi[k - 1]; bi[k - 1] = ti;
                        }
                    }
                }
            }
        };

        float md[KNN];
        int   mi[KNN];
#pragma unroll
        for (int k = 0; k < KNN; ++k) { md[k] = CUDART_INF_F; mi[k] = 0; }

        for (int l = 0; l < G; ++l) {
            int side = 2 * l + 1;
            int pairs = side * side;
            for (int pr = lane; pr < pairs; pr += 32) {
                int dz = pr / side - l;
                int dy = pr % side - l;
                int z = cz + dz, y = cy + dy;
                if (abs(dz) == l || abs(dy) == l) {
                    scan_run(z, y, cx - l, cx + l);
                } else {
                    scan_run(z, y, cx - l, cx - l);
                    scan_run(z, y, cx + l, cx + l);
                }
            }
            // Exact stop bound: merge all lanes' lists on lane 0.
            __syncwarp();
#pragma unroll
            for (int k = 0; k < KNN; ++k) {
                sdist[wslot][lane * KNN + k] = bd[k];
                sidx[wslot][lane * KNN + k] = bi[k];
            }
            __syncwarp();
            float kth;
            if (lane == 0) {
#pragma unroll
                for (int k = 0; k < KNN; ++k) { md[k] = CUDART_INF_F; mi[k] = 0; }
                for (int e = 0; e < 32 * KNN; ++e) {
                    float v = sdist[wslot][e];
                    if (v < md[KNN - 1]) {
                        md[KNN - 1] = v;
                        mi[KNN - 1] = sidx[wslot][e];
#pragma unroll
                        for (int k = KNN - 1; k > 0; --k) {
                            if (md[k] < md[k - 1]) {
                                float td = md[k]; md[k] = md[k - 1]; md[k - 1] = td;
                                int   ti = mi[k]; mi[k] = mi[k - 1]; mi[k - 1] = ti;
                            }
                        }
                    }
                }
                kth = md[KNN - 1];
            }
            kth = __shfl_sync(0xffffffffu, kth, 0);
            float bound = (float)l * hmin;
            if (q2 + kth < bound * bound - 0.05f) break;
        }

        if (lane == 0) {
            idw_store(flow, out, qi, q2, md, mi);
        }
        __syncwarp();
    }
}

extern "C" void kernel_launch(void* const* d_in, const int* in_sizes, int n_in,
                              void* d_out, int out_size) {
    const float* q = (const float*)d_in[0];
    const float* r = (const float*)d_in[1];
    const float* f = (const float*)d_in[2];
    int N = in_sizes[0] / 3;
    int M = in_sizes[1] / 3;
    if (M > MMAX) M = MMAX;
    if (N > NMAX) N = NMAX;

    zero_cells_kernel<<<NCELL / 256, 256>>>();
    bbox_kernel<<<1, 256>>>(r, M);
    hist_kernel<<<(M + N + 255) / 256, 256>>>(r, q, M, N);
    scan_kernel<<<2, 1024>>>(M, N);
    scatter_kernel<<<(M + N + 255) / 256, 256>>>(r, M, N);
    knn_easy_kernel<<<(N + 127) / 128, 128>>>(q, f, (float*)d_out, N);
    knn_hard_kernel<<<128, 256>>>(q, f, (float*)d_out);
}

// round 8
// speedup vs baseline: 2.4357x; 1.3190x over previous
#include <cuda_runtime.h>
#include <math_constants.h>

// Exact 8-NN IDW flow interpolation: uniform grid + expanding shells.
// Build pipeline fully multi-block (no single-SM kernels).
// Phase A: per-thread search limited to shells l<=2; Phase B: warp-per-query tail.
// Inputs: query_points [N,3] f32, ref_points [M,3] f32, ref_flow [M,3] f32 ; out [N,3] f32

#define NMAX  32768
#define MMAX  16384
#define KNN   8
#define G     32
#define NCELL (G * G * G)
#define LMAXA 2
#define CHUNK 512          // cells per scan block
#define NCHUNK (NCELL / CHUNK)   // 64

__device__ float4 g_pts[MMAX];
__device__ int    g_sid[MMAX];
__device__ int    g_cstart[NCELL + 1];
__device__ int    g_ccnt[NCELL];
__device__ int    g_ccur[NCELL];
__device__ int    g_cellof[MMAX];
__device__ int    g_qcnt[NCELL];
__device__ int    g_qcur[NCELL];
__device__ int    g_qstart[NCELL + 1];
__device__ int    g_qcell[NMAX];
__device__ int    g_qid[NMAX];
__device__ int    g_hard[NMAX];
__device__ int    g_hardcnt;
__device__ float  g_bb[8];            // [0..2]=min, [3..5]=1/h, [6]=hmin
__device__ int    g_bsum[2 * NCHUNK]; // chunk sums: [0..63]=ref, [64..127]=query
__device__ int    g_boff[2 * NCHUNK];
__device__ unsigned g_bbmin[3], g_bbmax[3];

// ---- order-preserving float<->uint for atomic min/max ----
__device__ __forceinline__ unsigned f2key(float f) {
    unsigned b = __float_as_uint(f);
    return b ^ ((b & 0x80000000u) ? 0xFFFFFFFFu : 0x80000000u);
}
__device__ __forceinline__ float key2f(unsigned k) {
    unsigned b = (k & 0x80000000u) ? (k ^ 0x80000000u) : ~k;
    return __uint_as_float(b);
}

__global__ void init_kernel() {
    int i = blockIdx.x * blockDim.x + threadIdx.x;
    if (i < NCELL) { g_ccnt[i] = 0; g_qcnt[i] = 0; }
    if (i == 0) {
        g_hardcnt = 0;
#pragma unroll
        for (int a = 0; a < 3; ++a) { g_bbmin[a] = 0xFFFFFFFFu; g_bbmax[a] = 0u; }
    }
}

// Parallel bbox: per-thread min/max -> block smem reduce -> 6 atomics per block.
__global__ void __launch_bounds__(256) bbox_atomic_kernel(
    const float* __restrict__ ref, int M)
{
    __shared__ float smn[3][64], smx[3][64];
    int t = threadIdx.x, lane = t & 31, wid = t >> 5;
    float mn[3] = {CUDART_INF_F, CUDART_INF_F, CUDART_INF_F};
    float mx[3] = {-CUDART_INF_F, -CUDART_INF_F, -CUDART_INF_F};
    for (int i = blockIdx.x * blockDim.x + t; i < M; i += gridDim.x * blockDim.x) {
#pragma unroll
        for (int a = 0; a < 3; ++a) {
            float v = ref[3 * i + a];
            mn[a] = fminf(mn[a], v);
            mx[a] = fmaxf(mx[a], v);
        }
    }
#pragma unroll
    for (int off = 16; off > 0; off >>= 1) {
#pragma unroll
        for (int a = 0; a < 3; ++a) {
            mn[a] = fminf(mn[a], __shfl_xor_sync(0xffffffffu, mn[a], off));
            mx[a] = fmaxf(mx[a], __shfl_xor_sync(0xffffffffu, mx[a], off));
        }
    }
    if (lane == 0) {
#pragma unroll
        for (int a = 0; a < 3; ++a) { smn[a][wid] = mn[a]; smx[a][wid] = mx[a]; }
    }
    __syncthreads();
    if (t == 0) {
        int nw = blockDim.x >> 5;
#pragma unroll
        for (int a = 0; a < 3; ++a) {
            float bmn = smn[a][0], bmx = smx[a][0];
            for (int w = 1; w < nw; ++w) {
                bmn = fminf(bmn, smn[a][w]);
                bmx = fmaxf(bmx, smx[a][w]);
            }
            atomicMin(&g_bbmin[a], f2key(bmn));
            atomicMax(&g_bbmax[a], f2key(bmx));
        }
    }
}

__global__ void bbox_finalize_kernel() {
    if (threadIdx.x == 0) {
        float hmin = CUDART_INF_F;
#pragma unroll
        for (int a = 0; a < 3; ++a) {
            float lo = key2f(g_bbmin[a]) - 1e-4f;
            float hi = key2f(g_bbmax[a]) + 1e-4f;
            float h = fmaxf((hi - lo) / (float)G, 1e-6f);
            g_bb[a] = lo;
            g_bb[3 + a] = 1.0f / h;
            hmin = fminf(hmin, h);
        }
        g_bb[6] = hmin;
    }
}

__device__ __forceinline__ int cell_of(float x, float y, float z) {
    int cx = (int)((x - g_bb[0]) * g_bb[3]);
    int cy = (int)((y - g_bb[1]) * g_bb[4]);
    int cz = (int)((z - g_bb[2]) * g_bb[5]);
    cx = min(G - 1, max(0, cx));
    cy = min(G - 1, max(0, cy));
    cz = min(G - 1, max(0, cz));
    return (cz * G + cy) * G + cx;
}

__global__ void hist_kernel(const float* __restrict__ ref,
                            const float* __restrict__ qp, int M, int N) {
    int i = blockIdx.x * blockDim.x + threadIdx.x;
    if (i < M) {
        int c = cell_of(ref[3 * i + 0], ref[3 * i + 1], ref[3 * i + 2]);
        g_cellof[i] = c;
        atomicAdd(&g_ccnt[c], 1);
    } else if (i < M + N) {
        int j = i - M;
        int c = cell_of(qp[3 * j + 0], qp[3 * j + 1], qp[3 * j + 2]);
        g_qcell[j] = c;
        atomicAdd(&g_qcnt[c], 1);
    }
}

// Scan phase 1: chunk sums. grid=2*NCHUNK blocks x 256 threads, 2 cells/thread.
__global__ void __launch_bounds__(256) scan1_kernel() {
    __shared__ int wsum[8];
    int b = blockIdx.x;
    const int* cnt = (b < NCHUNK) ? g_ccnt : g_qcnt;
    int c0 = (b & (NCHUNK - 1)) * CHUNK;
    int t = threadIdx.x, lane = t & 31, wid = t >> 5;

    int2 v = *(const int2*)&cnt[c0 + 2 * t];
    int s = v.x + v.y;
#pragma unroll
    for (int off = 16; off > 0; off >>= 1)
        s += __shfl_xor_sync(0xffffffffu, s, off);
    if (lane == 0) wsum[wid] = s;
    __syncthreads();
    if (t == 0) {
        int tot = 0;
#pragma unroll
        for (int w = 0; w < 8; ++w) tot += wsum[w];
        g_bsum[b] = tot;
    }
}

// Scan phase 2: scan the 2 x 64 chunk sums. One block, 64 threads (2 warps).
__global__ void __launch_bounds__(64) scan2_kernel(int M, int N) {
    int t = threadIdx.x, lane = t & 31, w = t >> 5;  // w: 0=ref, 1=query
    int base = w * NCHUNK;
    int v0 = g_bsum[base + 2 * lane];
    int v1 = g_bsum[base + 2 * lane + 1];
    int s = v0 + v1;
    int inc = s;
#pragma unroll
    for (int off = 1; off < 32; off <<= 1) {
        int u = __shfl_up_sync(0xffffffffu, inc, off);
        if (lane >= off) inc += u;
    }
    int ex = inc - s;
    g_boff[base + 2 * lane] = ex;
    g_boff[base + 2 * lane + 1] = ex + v0;
    if (lane == 31) {
        if (w == 0) g_cstart[NCELL] = M;
        else        g_qstart[NCELL] = N;
    }
}

// Scan phase 3: local exclusive scan per chunk + global offset; write start/cur.
__global__ void __launch_bounds__(256) scan3_kernel() {
    __shared__ int wsum[8];
    int b = blockIdx.x;
    bool isq = (b >= NCHUNK);
    const int* cnt = isq ? g_qcnt : g_ccnt;
    int* start = isq ? g_qstart : g_cstart;
    int* cur   = isq ? g_qcur   : g_ccur;
    int c0 = (b & (NCHUNK - 1)) * CHUNK;
    int t = threadIdx.x, lane = t & 31, wid = t >> 5;

    int2 v = *(const int2*)&cnt[c0 + 2 * t];
    int s = v.x + v.y;
    int inc = s;
#pragma unroll
    for (int off = 1; off < 32; off <<= 1) {
        int u = __shfl_up_sync(0xffffffffu, inc, off);
        if (lane >= off) inc += u;
    }
    if (lane == 31) wsum[wid] = inc;
    __syncthreads();
    if (wid == 0 && lane < 8) {
        int w = wsum[lane];
#pragma unroll
        for (int off = 1; off < 8; off <<= 1) {
            int u = __shfl_up_sync(0xffu, w, off);
            if (lane >= off) w += u;
        }
        wsum[lane] = w;
    }
    __syncthreads();
    int ex = inc - s + (wid ? wsum[wid - 1] : 0) + g_boff[b];
    int2 st = make_int2(ex, ex + v.x);
    *(int2*)&start[c0 + 2 * t] = st;
    *(int2*)&cur[c0 + 2 * t] = st;
}

__global__ void scatter_kernel(const float* __restrict__ ref, int M, int N) {
    int i = blockIdx.x * blockDim.x + threadIdx.x;
    if (i < M) {
        float x = ref[3 * i + 0];
        float y = ref[3 * i + 1];
        float z = ref[3 * i + 2];
        int c = g_cellof[i];
        int p = atomicAdd(&g_ccur[c], 1);
        g_pts[p] = make_float4(x, y, z, fmaf(x, x, fmaf(y, y, z * z)));
        g_sid[p] = i;
    } else if (i < M + N) {
        int j = i - M;
        int c = g_qcell[j];
        int p = atomicAdd(&g_qcur[c], 1);
        g_qid[p] = j;
    }
}

__device__ __forceinline__ void idw_store(
    const float* __restrict__ flow, float* __restrict__ out,
    int qi, float q2, const float* bd, const int* bi)
{
    float wsum = 0.f, ox = 0.f, oy = 0.f, oz = 0.f;
#pragma unroll
    for (int k = 0; k < KNN; ++k) {
        float d2 = fmaxf(q2 + bd[k], 0.0f);
        float w = 1.0f / (d2 + 1e-8f);
        int id = bi[k];
        ox = fmaf(w, flow[3 * id + 0], ox);
        oy = fmaf(w, flow[3 * id + 1], oy);
        oz = fmaf(w, flow[3 * id + 2], oz);
        wsum += w;
    }
    float inv = 1.0f / wsum;
    out[3 * qi + 0] = ox * inv;
    out[3 * qi + 1] = oy * inv;
    out[3 * qi + 2] = oz * inv;
}

// Phase A: per-thread, shells l<=LMAXA. Unresolved queries go to the hard list.
__global__ void __launch_bounds__(128) knn_easy_kernel(
    const float* __restrict__ qpts,
    const float* __restrict__ flow,
    float* __restrict__ out, int N)
{
    int tq = blockIdx.x * blockDim.x + threadIdx.x;
    if (tq >= N) return;
    int qi = g_qid[tq];

    const float qx = qpts[3 * qi + 0];
    const float qy = qpts[3 * qi + 1];
    const float qz = qpts[3 * qi + 2];
    const float nqx = -2.0f * qx;
    const float nqy = -2.0f * qy;
    const float nqz = -2.0f * qz;
    const float q2 = fmaf(qx, qx, fmaf(qy, qy, qz * qz));
    const float hmin = g_bb[6];

    int cx = (int)((qx - g_bb[0]) * g_bb[3]);
    int cy = (int)((qy - g_bb[1]) * g_bb[4]);
    int cz = (int)((qz - g_bb[2]) * g_bb[5]);
    cx = min(G - 1, max(0, cx));
    cy = min(G - 1, max(0, cy));
    cz = min(G - 1, max(0, cz));

    float bd[KNN];
    int   bi[KNN];
#pragma unroll
    for (int k = 0; k < KNN; ++k) { bd[k] = CUDART_INF_F; bi[k] = 0; }

    auto do_row = [&](int z, int y, int x0, int x1) {
        if ((unsigned)z >= G || (unsigned)y >= G) return;
        x0 = max(x0, 0);
        x1 = min(x1, G - 1);
        if (x0 > x1) return;
        int rb = (z * G + y) * G;
        int s = g_cstart[rb + x0];
        int e = g_cstart[rb + x1 + 1];
        for (int p = s; p < e; ++p) {
            float4 r = g_pts[p];
            float sc = fmaf(r.x, nqx, fmaf(r.y, nqy, fmaf(r.z, nqz, r.w)));
            if (sc < bd[KNN - 1]) {
                bd[KNN - 1] = sc;
                bi[KNN - 1] = g_sid[p];
#pragma unroll
                for (int k = KNN - 1; k > 0; --k) {
                    if (bd[k] < bd[k - 1]) {
                        float td = bd[k]; bd[k] = bd[k - 1]; bd[k - 1] = td;
                        int   ti = bi[k]; bi[k] = bi[k - 1]; bi[k - 1] = ti;
                    }
                }
            }
        }
    };

    bool done = false;
    for (int l = 0; l <= LMAXA; ++l) {
        if (l == 0) {
            do_row(cz, cy, cx, cx);
        } else {
            for (int y = cy - l; y <= cy + l; ++y) {
                do_row(cz - l, y, cx - l, cx + l);
                do_row(cz + l, y, cx - l, cx + l);
            }
            for (int z = cz - l + 1; z <= cz + l - 1; ++z) {
                do_row(z, cy - l, cx - l, cx + l);
                do_row(z, cy + l, cx - l, cx + l);
                for (int y = cy - l + 1; y <= cy + l - 1; ++y) {
                    do_row(z, y, cx - l, cx - l);
                    do_row(z, y, cx + l, cx + l);
                }
            }
        }
        float bound = (float)l * hmin;
        if (q2 + bd[KNN - 1] < bound * bound - 0.05f) { done = true; break; }
    }

    if (done) {
        idw_store(flow, out, qi, q2, bd, bi);
    } else {
        int slot = atomicAdd(&g_hardcnt, 1);
        g_hard[slot] = qi;
    }
}

// Phase B: one warp per hard query; lanes split shell rows; per-shell exact merge.
__global__ void __launch_bounds__(256) knn_hard_kernel(
    const float* __restrict__ qpts,
    const float* __restrict__ flow,
    float* __restrict__ out)
{
    __shared__ float sdist[8][32 * KNN];
    __shared__ int   sidx[8][32 * KNN];

    int lane = threadIdx.x & 31;
    int wslot = threadIdx.x >> 5;
    int wgid = (blockIdx.x * blockDim.x + threadIdx.x) >> 5;
    int nwarps = (gridDim.x * blockDim.x) >> 5;
    int hcnt = g_hardcnt;
    const float hmin = g_bb[6];

    for (int h = wgid; h < hcnt; h += nwarps) {
        int qi = g_hard[h];
        const float qx = qpts[3 * qi + 0];
        const float qy = qpts[3 * qi + 1];
        const float qz = qpts[3 * qi + 2];
        const float nqx = -2.0f * qx;
        const float nqy = -2.0f * qy;
        const float nqz = -2.0f * qz;
        const float q2 = fmaf(qx, qx, fmaf(qy, qy, qz * qz));

        int cx = (int)((qx - g_bb[0]) * g_bb[3]);
        int cy = (int)((qy - g_bb[1]) * g_bb[4]);
        int cz = (int)((qz - g_bb[2]) * g_bb[5]);
        cx = min(G - 1, max(0, cx));
        cy = min(G - 1, max(0, cy));
        cz = min(G - 1, max(0, cz));

        float bd[KNN];
        int   bi[KNN];
#pragma unroll
        for (int k = 0; k < KNN; ++k) { bd[k] = CUDART_INF_F; bi[k] = 0; }

        auto scan_run = [&](int z, int y, int x0, int x1) {
            if ((unsigned)z >= G || (unsigned)y >= G) return;
            x0 = max(x0, 0);
            x1 = min(x1, G - 1);
            if (x0 > x1) return;
            int rb = (z * G + y) * G;
            int s = g_cstart[rb + x0];
            int e = g_cstart[rb + x1 + 1];
            for (int p = s; p < e; ++p) {
                float4 r = g_pts[p];
                float sc = fmaf(r.x, nqx, fmaf(r.y, nqy, fmaf(r.z, nqz, r.w)));
                if (sc < bd[KNN - 1]) {
                    bd[KNN - 1] = sc;
                    bi[KNN - 1] = g_sid[p];
#pragma unroll
                    for (int k = KNN - 1; k > 0; --k) {
                        if (bd[k] < bd[k - 1]) {
                            float td = bd[k]; bd[k] = bd[k - 1]; bd[k - 1] = td;
                            int   ti = bi[k]; bi[k] = bi[k - 1]; bi[k - 1] = ti;
                        }
                    }
                }
            }
        };

        float md[KNN];
        int   mi[KNN];
#pragma unroll
        for (int k = 0; k < KNN; ++k) { md[k] = CUDART_INF_F; mi[k] = 0; }

        for (int l = 0; l < G; ++l) {
            int side = 2 * l + 1;
            int pairs = side * side;
            for (int pr = lane; pr < pairs; pr += 32) {
                int dz = pr / side - l;
                int dy = pr % side - l;
                int z = cz + dz, y = cy + dy;
                if (abs(dz) == l || abs(dy) == l) {
                    scan_run(z, y, cx - l, cx + l);
                } else {
                    scan_run(z, y, cx - l, cx - l);
                    scan_run(z, y, cx + l, cx + l);
                }
            }
            __syncwarp();
#pragma unroll
            for (int k = 0; k < KNN; ++k) {
                sdist[wslot][lane * KNN + k] = bd[k];
                sidx[wslot][lane * KNN + k] = bi[k];
            }
            __syncwarp();
            float kth;
            if (lane == 0) {
#pragma unroll
                for (int k = 0; k < KNN; ++k) { md[k] = CUDART_INF_F; mi[k] = 0; }
                for (int e = 0; e < 32 * KNN; ++e) {
                    float v = sdist[wslot][e];
                    if (v < md[KNN - 1]) {
                        md[KNN - 1] = v;
                        mi[KNN - 1] = sidx[wslot][e];
#pragma unroll
                        for (int k = KNN - 1; k > 0; --k) {
                            if (md[k] < md[k - 1]) {
                                float td = md[k]; md[k] = md[k - 1]; md[k - 1] = td;
                                int   ti = mi[k]; mi[k] = mi[k - 1]; mi[k - 1] = ti;
                            }
                        }
                    }
                }
                kth = md[KNN - 1];
            }
            kth = __shfl_sync(0xffffffffu, kth, 0);
            float bound = (float)l * hmin;
            if (q2 + kth < bound * bound - 0.05f) break;
        }

        if (lane == 0) {
            idw_store(flow, out, qi, q2, md, mi);
        }
        __syncwarp();
    }
}

extern "C" void kernel_launch(void* const* d_in, const int* in_sizes, int n_in,
                              void* d_out, int out_size) {
    const float* q = (const float*)d_in[0];
    const float* r = (const float*)d_in[1];
    const float* f = (const float*)d_in[2];
    int N = in_sizes[0] / 3;
    int M = in_sizes[1] / 3;
    if (M > MMAX) M = MMAX;
    if (N > NMAX) N = NMAX;

    init_kernel<<<NCELL / 256, 256>>>();
    bbox_atomic_kernel<<<64, 256>>>(r, M);
    bbox_finalize_kernel<<<1, 32>>>();
    hist_kernel<<<(M + N + 255) / 256, 256>>>(r, q, M, N);
    scan1_kernel<<<2 * NCHUNK, 256>>>();
    scan2_kernel<<<1, 64>>>(M, N);
    scan3_kernel<<<2 * NCHUNK, 256>>>();
    scatter_kernel<<<(M + N + 255) / 256, 256>>>(r, M, N);
    knn_easy_kernel<<<(N + 127) / 128, 128>>>(q, f, (float*)d_out, N);
    knn_hard_kernel<<<128, 256>>>(q, f, (float*)d_out);
}

// round 9
// speedup vs baseline: 2.5659x; 1.0535x over previous
#include <cuda_runtime.h>
#include <math_constants.h>

// Exact 8-NN IDW flow interpolation: uniform grid + expanding shells.
// Phase A: per-thread, box l<=1 then shell l=2, batch-4 candidate scans.
// Phase B: warp-per-query tail. Build pipeline fully multi-block, 8 launches.
// Inputs: query_points [N,3] f32, ref_points [M,3] f32, ref_flow [M,3] f32 ; out [N,3] f32

#define NMAX  32768
#define MMAX  16384
#define KNN   8
#define G     32
#define NCELL (G * G * G)
#define CHUNK 512
#define NCHUNK (NCELL / CHUNK)   // 64

__device__ float4 g_pts[MMAX];
__device__ int    g_sid[MMAX];
__device__ int    g_cstart[NCELL + 1];
__device__ int    g_ccnt[NCELL];
__device__ int    g_ccur[NCELL];
__device__ int    g_cellof[MMAX];
__device__ int    g_qcnt[NCELL];
__device__ int    g_qcur[NCELL];
__device__ int    g_qcell[NMAX];
__device__ float4 g_qs[NMAX];          // cell-sorted query coords (x,y,z,|q|^2)
__device__ int    g_qid[NMAX];         // sorted slot -> original query index
__device__ int    g_hard[NMAX];        // sorted slots of unresolved queries
__device__ int    g_hardcnt;
__device__ float  g_bb[8];             // [0..2]=min, [3..5]=1/h, [6]=hmin
__device__ int    g_bsum[2 * NCHUNK];
__device__ unsigned g_bbmin[3], g_bbmax[3];
__device__ int    g_bbdone;

__device__ __forceinline__ unsigned f2key(float f) {
    unsigned b = __float_as_uint(f);
    return b ^ ((b & 0x80000000u) ? 0xFFFFFFFFu : 0x80000000u);
}
__device__ __forceinline__ float key2f(unsigned k) {
    unsigned b = (k & 0x80000000u) ? (k ^ 0x80000000u) : ~k;
    return __uint_as_float(b);
}

__global__ void init_kernel() {
    int i = blockIdx.x * blockDim.x + threadIdx.x;
    if (i < NCELL) { g_ccnt[i] = 0; g_qcnt[i] = 0; }
    if (i == 0) {
        g_hardcnt = 0;
        g_bbdone = 0;
#pragma unroll
        for (int a = 0; a < 3; ++a) { g_bbmin[a] = 0xFFFFFFFFu; g_bbmax[a] = 0u; }
    }
}

// Parallel bbox with last-block finalize.
__global__ void __launch_bounds__(256) bbox_kernel(const float* __restrict__ ref, int M) {
    __shared__ float smn[3][8], smx[3][8];
    int t = threadIdx.x, lane = t & 31, wid = t >> 5;
    float mn[3] = {CUDART_INF_F, CUDART_INF_F, CUDART_INF_F};
    float mx[3] = {-CUDART_INF_F, -CUDART_INF_F, -CUDART_INF_F};
    for (int i = blockIdx.x * blockDim.x + t; i < M; i += gridDim.x * blockDim.x) {
#pragma unroll
        for (int a = 0; a < 3; ++a) {
            float v = ref[3 * i + a];
            mn[a] = fminf(mn[a], v);
            mx[a] = fmaxf(mx[a], v);
        }
    }
#pragma unroll
    for (int off = 16; off > 0; off >>= 1) {
#pragma unroll
        for (int a = 0; a < 3; ++a) {
            mn[a] = fminf(mn[a], __shfl_xor_sync(0xffffffffu, mn[a], off));
            mx[a] = fmaxf(mx[a], __shfl_xor_sync(0xffffffffu, mx[a], off));
        }
    }
    if (lane == 0) {
#pragma unroll
        for (int a = 0; a < 3; ++a) { smn[a][wid] = mn[a]; smx[a][wid] = mx[a]; }
    }
    __syncthreads();
    if (t == 0) {
#pragma unroll
        for (int a = 0; a < 3; ++a) {
            float bmn = smn[a][0], bmx = smx[a][0];
            for (int w = 1; w < 8; ++w) {
                bmn = fminf(bmn, smn[a][w]);
                bmx = fmaxf(bmx, smx[a][w]);
            }
            atomicMin(&g_bbmin[a], f2key(bmn));
            atomicMax(&g_bbmax[a], f2key(bmx));
        }
        __threadfence();
        int done = atomicAdd(&g_bbdone, 1);
        if (done == gridDim.x - 1) {   // last block finalizes
            float hmin = CUDART_INF_F;
#pragma unroll
            for (int a = 0; a < 3; ++a) {
                float lo = key2f(g_bbmin[a]) - 1e-4f;
                float hi = key2f(g_bbmax[a]) + 1e-4f;
                float h = fmaxf((hi - lo) / (float)G, 1e-6f);
                g_bb[a] = lo;
                g_bb[3 + a] = 1.0f / h;
                hmin = fminf(hmin, h);
            }
            g_bb[6] = hmin;
        }
    }
}

__device__ __forceinline__ int cell_of(float x, float y, float z) {
    int cx = (int)((x - g_bb[0]) * g_bb[3]);
    int cy = (int)((y - g_bb[1]) * g_bb[4]);
    int cz = (int)((z - g_bb[2]) * g_bb[5]);
    cx = min(G - 1, max(0, cx));
    cy = min(G - 1, max(0, cy));
    cz = min(G - 1, max(0, cz));
    return (cz * G + cy) * G + cx;
}

__global__ void hist_kernel(const float* __restrict__ ref,
                            const float* __restrict__ qp, int M, int N) {
    int i = blockIdx.x * blockDim.x + threadIdx.x;
    if (i < M) {
        int c = cell_of(ref[3 * i + 0], ref[3 * i + 1], ref[3 * i + 2]);
        g_cellof[i] = c;
        atomicAdd(&g_ccnt[c], 1);
    } else if (i < M + N) {
        int j = i - M;
        int c = cell_of(qp[3 * j + 0], qp[3 * j + 1], qp[3 * j + 2]);
        g_qcell[j] = c;
        atomicAdd(&g_qcnt[c], 1);
    }
}

// Scan phase 1: chunk sums (2*NCHUNK blocks).
__global__ void __launch_bounds__(256) scan1_kernel() {
    __shared__ int wsum[8];
    int b = blockIdx.x;
    const int* cnt = (b < NCHUNK) ? g_ccnt : g_qcnt;
    int c0 = (b & (NCHUNK - 1)) * CHUNK;
    int t = threadIdx.x, lane = t & 31, wid = t >> 5;
    int2 v = *(const int2*)&cnt[c0 + 2 * t];
    int s = v.x + v.y;
#pragma unroll
    for (int off = 16; off > 0; off >>= 1)
        s += __shfl_xor_sync(0xffffffffu, s, off);
    if (lane == 0) wsum[wid] = s;
    __syncthreads();
    if (t == 0) {
        int tot = 0;
#pragma unroll
        for (int w = 0; w < 8; ++w) tot += wsum[w];
        g_bsum[b] = tot;
    }
}

// Scan phase 2: each block redundantly scans its half's 64 chunk sums (warp 0),
// then local exclusive scan + offset; writes start/cur as int2.
__global__ void __launch_bounds__(256) scan2_kernel(int M, int N) {
    __shared__ int wsum[8];
    __shared__ int chunk_off;
    int b = blockIdx.x;
    bool isq = (b >= NCHUNK);
    const int* cnt = isq ? g_qcnt : g_ccnt;
    int* start = isq ? (int*)nullptr : g_cstart;   // start array selected below
    int* s_arr = isq ? g_qcur /*placeholder*/ : g_cstart;
    (void)start; (void)s_arr;
    int t = threadIdx.x, lane = t & 31, wid = t >> 5;

    if (wid == 0) {   // warp-scan the 64 chunk sums of this half
        int base = (isq ? NCHUNK : 0);
        int v0 = g_bsum[base + 2 * lane];
        int v1 = g_bsum[base + 2 * lane + 1];
        int s = v0 + v1;
        int inc = s;
#pragma unroll
        for (int off = 1; off < 32; off <<= 1) {
            int u = __shfl_up_sync(0xffffffffu, inc, off);
            if (lane >= off) inc += u;
        }
        int ex = inc - s;   // exclusive prefix of chunk 2*lane
        int myc = b & (NCHUNK - 1);
        int want0 = myc >> 1;
        int sel = __shfl_sync(0xffffffffu, ex, want0);
        int selv0 = __shfl_sync(0xffffffffu, v0, want0);
        if (lane == 0) chunk_off = (myc & 1) ? (sel + selv0) : sel;
    }
    __syncthreads();

    const int c0 = (b & (NCHUNK - 1)) * CHUNK;
    int2 v = *(const int2*)&cnt[c0 + 2 * t];
    int s = v.x + v.y;
    int inc = s;
#pragma unroll
    for (int off = 1; off < 32; off <<= 1) {
        int u = __shfl_up_sync(0xffffffffu, inc, off);
        if (lane >= off) inc += u;
    }
    if (lane == 31) wsum[wid] = inc;
    __syncthreads();
    if (wid == 0 && lane < 8) {
        int w = wsum[lane];
#pragma unroll
        for (int off = 1; off < 8; off <<= 1) {
            int u = __shfl_up_sync(0xffu, w, off);
            if (lane >= off) w += u;
        }
        wsum[lane] = w;
    }
    __syncthreads();
    int ex = inc - s + (wid ? wsum[wid - 1] : 0) + chunk_off;
    int2 st = make_int2(ex, ex + v.x);
    if (isq) {
        *(int2*)&g_qcur[c0 + 2 * t] = st;
    } else {
        *(int2*)&g_cstart[c0 + 2 * t] = st;
        *(int2*)&g_ccur[c0 + 2 * t] = st;
    }
    if (!isq && b == 0 && t == 0) g_cstart[NCELL] = M;
}

__global__ void scatter_kernel(const float* __restrict__ ref,
                               const float* __restrict__ qp, int M, int N) {
    int i = blockIdx.x * blockDim.x + threadIdx.x;
    if (i < M) {
        float x = ref[3 * i + 0];
        float y = ref[3 * i + 1];
        float z = ref[3 * i + 2];
        int c = g_cellof[i];
        int p = atomicAdd(&g_ccur[c], 1);
        g_pts[p] = make_float4(x, y, z, fmaf(x, x, fmaf(y, y, z * z)));
        g_sid[p] = i;
    } else if (i < M + N) {
        int j = i - M;
        float x = qp[3 * j + 0];
        float y = qp[3 * j + 1];
        float z = qp[3 * j + 2];
        int c = g_qcell[j];
        int p = atomicAdd(&g_qcur[c], 1);
        g_qs[p] = make_float4(x, y, z, fmaf(x, x, fmaf(y, y, z * z)));
        g_qid[p] = j;
    }
}

__device__ __forceinline__ void idw_store(
    const float* __restrict__ flow, float* __restrict__ out,
    int qi, float q2, const float* bd, const int* bi)
{
    float wsum = 0.f, ox = 0.f, oy = 0.f, oz = 0.f;
#pragma unroll
    for (int k = 0; k < KNN; ++k) {
        float d2 = fmaxf(q2 + bd[k], 0.0f);
        float w = 1.0f / (d2 + 1e-8f);
        int id = bi[k];
        ox = fmaf(w, flow[3 * id + 0], ox);
        oy = fmaf(w, flow[3 * id + 1], oy);
        oz = fmaf(w, flow[3 * id + 2], oz);
        wsum += w;
    }
    float inv = 1.0f / wsum;
    out[3 * qi + 0] = ox * inv;
    out[3 * qi + 1] = oy * inv;
    out[3 * qi + 2] = oz * inv;
}

// Phase A: per-thread; box l<=1 then shell l=2; batch-4 scans for MLP.
__global__ void __launch_bounds__(128) knn_easy_kernel(
    const float* __restrict__ flow,
    float* __restrict__ out, int N)
{
    int tq = blockIdx.x * blockDim.x + threadIdx.x;
    if (tq >= N) return;

    float4 qv = g_qs[tq];
    const float nqx = -2.0f * qv.x;
    const float nqy = -2.0f * qv.y;
    const float nqz = -2.0f * qv.z;
    const float q2 = qv.w;
    const float hmin = g_bb[6];

    int cx = (int)((qv.x - g_bb[0]) * g_bb[3]);
    int cy = (int)((qv.y - g_bb[1]) * g_bb[4]);
    int cz = (int)((qv.z - g_bb[2]) * g_bb[5]);
    cx = min(G - 1, max(0, cx));
    cy = min(G - 1, max(0, cy));
    cz = min(G - 1, max(0, cz));

    float bd[KNN];
    int   bi[KNN];
#pragma unroll
    for (int k = 0; k < KNN; ++k) { bd[k] = CUDART_INF_F; bi[k] = 0; }

    auto ins = [&](float sc, int p) {
        if (sc < bd[KNN - 1]) {
            bd[KNN - 1] = sc;
            bi[KNN - 1] = g_sid[p];
#pragma unroll
            for (int k = KNN - 1; k > 0; --k) {
                if (bd[k] < bd[k - 1]) {
                    float td = bd[k]; bd[k] = bd[k - 1]; bd[k - 1] = td;
                    int   ti = bi[k]; bi[k] = bi[k - 1]; bi[k - 1] = ti;
                }
            }
        }
    };

    auto do_row = [&](int z, int y, int x0, int x1) {
        if ((unsigned)z >= G || (unsigned)y >= G) return;
        x0 = max(x0, 0);
        x1 = min(x1, G - 1);
        if (x0 > x1) return;
        int rb = (z * G + y) * G;
        int p = g_cstart[rb + x0];
        int e = g_cstart[rb + x1 + 1];
        for (; p + 4 <= e; p += 4) {
            float4 r0 = g_pts[p + 0];
            float4 r1 = g_pts[p + 1];
            float4 r2 = g_pts[p + 2];
            float4 r3 = g_pts[p + 3];
            float s0 = fmaf(r0.x, nqx, fmaf(r0.y, nqy, fmaf(r0.z, nqz, r0.w)));
            float s1 = fmaf(r1.x, nqx, fmaf(r1.y, nqy, fmaf(r1.z, nqz, r1.w)));
            float s2 = fmaf(r2.x, nqx, fmaf(r2.y, nqy, fmaf(r2.z, nqz, r2.w)));
            float s3 = fmaf(r3.x, nqx, fmaf(r3.y, nqy, fmaf(r3.z, nqz, r3.w)));
            float m = fminf(fminf(s0, s1), fminf(s2, s3));
            if (m < bd[KNN - 1]) {
                ins(s0, p); ins(s1, p + 1); ins(s2, p + 2); ins(s3, p + 3);
            }
        }
        for (; p < e; ++p) {
            float4 r = g_pts[p];
            float sc = fmaf(r.x, nqx, fmaf(r.y, nqy, fmaf(r.z, nqz, r.w)));
            ins(sc, p);
        }
    };

    // Box l<=1 (bound after l=0 can never fire, so scan it as one box).
    for (int dz = -1; dz <= 1; ++dz)
        for (int dy = -1; dy <= 1; ++dy)
            do_row(cz + dz, cy + dy, cx - 1, cx + 1);

    bool done = (q2 + bd[KNN - 1] < hmin * hmin - 0.05f);
    if (!done) {
        // Shell l=2.
        for (int dy = -2; dy <= 2; ++dy) {
            do_row(cz - 2, cy + dy, cx - 2, cx + 2);
            do_row(cz + 2, cy + dy, cx - 2, cx + 2);
        }
        for (int dz = -1; dz <= 1; ++dz) {
            do_row(cz + dz, cy - 2, cx - 2, cx + 2);
            do_row(cz + dz, cy + 2, cx - 2, cx + 2);
            for (int dy = -1; dy <= 1; ++dy) {
                do_row(cz + dz, cy + dy, cx - 2, cx - 2);
                do_row(cz + dz, cy + dy, cx + 2, cx + 2);
            }
        }
        float bound = 2.0f * hmin;
        done = (q2 + bd[KNN - 1] < bound * bound - 0.05f);
    }

    if (done) {
        idw_store(flow, out, g_qid[tq], q2, bd, bi);
    } else {
        int slot = atomicAdd(&g_hardcnt, 1);
        g_hard[slot] = tq;
    }
}

// Phase B: one warp per hard query; lanes split shell rows; per-shell exact merge.
__global__ void __launch_bounds__(256) knn_hard_kernel(
    const float* __restrict__ flow,
    float* __restrict__ out)
{
    __shared__ float sdist[8][32 * KNN];
    __shared__ int   sidx[8][32 * KNN];

    int lane = threadIdx.x & 31;
    int wslot = threadIdx.x >> 5;
    int wgid = (blockIdx.x * blockDim.x + threadIdx.x) >> 5;
    int nwarps = (gridDim.x * blockDim.x) >> 5;
    int hcnt = g_hardcnt;
    const float hmin = g_bb[6];

    for (int h = wgid; h < hcnt; h += nwarps) {
        int tq = g_hard[h];
        float4 qv = g_qs[tq];
        const float nqx = -2.0f * qv.x;
        const float nqy = -2.0f * qv.y;
        const float nqz = -2.0f * qv.z;
        const float q2 = qv.w;

        int cx = (int)((qv.x - g_bb[0]) * g_bb[3]);
        int cy = (int)((qv.y - g_bb[1]) * g_bb[4]);
        int cz = (int)((qv.z - g_bb[2]) * g_bb[5]);
        cx = min(G - 1, max(0, cx));
        cy = min(G - 1, max(0, cy));
        cz = min(G - 1, max(0, cz));

        float bd[KNN];
        int   bi[KNN];
#pragma unroll
        for (int k = 0; k < KNN; ++k) { bd[k] = CUDART_INF_F; bi[k] = 0; }

        auto ins = [&](float sc, int p) {
            if (sc < bd[KNN - 1]) {
                bd[KNN - 1] = sc;
                bi[KNN - 1] = g_sid[p];
#pragma unroll
                for (int k = KNN - 1; k > 0; --k) {
                    if (bd[k] < bd[k - 1]) {
                        float td = bd[k]; bd[k] = bd[k - 1]; bd[k - 1] = td;
                        int   ti = bi[k]; bi[k] = bi[k - 1]; bi[k - 1] = ti;
                    }
                }
            }
        };

        auto scan_run = [&](int z, int y, int x0, int x1) {
            if ((unsigned)z >= G || (unsigned)y >= G) return;
            x0 = max(x0, 0);
            x1 = min(x1, G - 1);
            if (x0 > x1) return;
            int rb = (z * G + y) * G;
            int p = g_cstart[rb + x0];
            int e = g_cstart[rb + x1 + 1];
            for (; p + 4 <= e; p += 4) {
                float4 r0 = g_pts[p + 0];
                float4 r1 = g_pts[p + 1];
                float4 r2 = g_pts[p + 2];
                float4 r3 = g_pts[p + 3];
                float s0 = fmaf(r0.x, nqx, fmaf(r0.y, nqy, fmaf(r0.z, nqz, r0.w)));
                float s1 = fmaf(r1.x, nqx, fmaf(r1.y, nqy, fmaf(r1.z, nqz, r1.w)));
                float s2 = fmaf(r2.x, nqx, fmaf(r2.y, nqy, fmaf(r2.z, nqz, r2.w)));
                float s3 = fmaf(r3.x, nqx, fmaf(r3.y, nqy, fmaf(r3.z, nqz, r3.w)));
                float m = fminf(fminf(s0, s1), fminf(s2, s3));
                if (m < bd[KNN - 1]) {
                    ins(s0, p); ins(s1, p + 1); ins(s2, p + 2); ins(s3, p + 3);
                }
            }
            for (; p < e; ++p) {
                float4 r = g_pts[p];
                float sc = fmaf(r.x, nqx, fmaf(r.y, nqy, fmaf(r.z, nqz, r.w)));
                ins(sc, p);
            }
        };

        float md[KNN];
        int   mi[KNN];
#pragma unroll
        for (int k = 0; k < KNN; ++k) { md[k] = CUDART_INF_F; mi[k] = 0; }

        for (int l = 0; l < G; ++l) {
            int side = 2 * l + 1;
            int pairs = side * side;
            for (int pr = lane; pr < pairs; pr += 32) {
                int dz = pr / side - l;
                int dy = pr % side - l;
                int z = cz + dz, y = cy + dy;
                if (abs(dz) == l || abs(dy) == l) {
                    scan_run(z, y, cx - l, cx + l);
                } else {
                    scan_run(z, y, cx - l, cx - l);
                    scan_run(z, y, cx + l, cx + l);
                }
            }
            __syncwarp();
#pragma unroll
            for (int k = 0; k < KNN; ++k) {
                sdist[wslot][lane * KNN + k] = bd[k];
                sidx[wslot][lane * KNN + k] = bi[k];
            }
            __syncwarp();
            float kth;
            if (lane == 0) {
#pragma unroll
                for (int k = 0; k < KNN; ++k) { md[k] = CUDART_INF_F; mi[k] = 0; }
                for (int e = 0; e < 32 * KNN; ++e) {
                    float v = sdist[wslot][e];
                    if (v < md[KNN - 1]) {
                        md[KNN - 1] = v;
                        mi[KNN - 1] = sidx[wslot][e];
#pragma unroll
                        for (int k = KNN - 1; k > 0; --k) {
                            if (md[k] < md[k - 1]) {
                                float td = md[k]; md[k] = md[k - 1]; md[k - 1] = td;
                                int   ti = mi[k]; mi[k] = mi[k - 1]; mi[k - 1] = ti;
                            }
                        }
                    }
                }
                kth = md[KNN - 1];
            }
            kth = __shfl_sync(0xffffffffu, kth, 0);
            float bound = (float)l * hmin;
            if (q2 + kth < bound * bound - 0.05f) break;
        }

        if (lane == 0) {
            idw_store(flow, out, g_qid[tq], q2, md, mi);
        }
        __syncwarp();
    }
}

extern "C" void kernel_launch(void* const* d_in, const int* in_sizes, int n_in,
                              void* d_out, int out_size) {
    const float* q = (const float*)d_in[0];
    const float* r = (const float*)d_in[1];
    const float* f = (const float*)d_in[2];
    int N = in_sizes[0] / 3;
    int M = in_sizes[1] / 3;
    if (M > MMAX) M = MMAX;
    if (N > NMAX) N = NMAX;

    init_kernel<<<NCELL / 256, 256>>>();
    bbox_kernel<<<64, 256>>>(r, M);
    hist_kernel<<<(M + N + 255) / 256, 256>>>(r, q, M, N);
    scan1_kernel<<<2 * NCHUNK, 256>>>();
    scan2_kernel<<<2 * NCHUNK, 256>>>(M, N);
    scatter_kernel<<<(M + N + 255) / 256, 256>>>(r, q, M, N);
    knn_easy_kernel<<<(N + 127) / 128, 128>>>(f, (float*)d_out, N);
    knn_hard_kernel<<<128, 256>>>(f, (float*)d_out);
}